// round 11
// baseline (speedup 1.0000x reference)
#include <cuda_runtime.h>
#include <cstdint>
#include <cstddef>

// Problem constants (fixed by reference: N=256, C=2048, H=16, W=8, K=13)
#define KPT   13
#define HW_   128
#define CCH   2048
#define NBAT  256
#define TC    128     // channels per CTA
#define NTHR  256

typedef unsigned long long ull;

__device__ __forceinline__ void upk2(ull v, float &lo, float &hi) {
    asm("mov.b64 {%0, %1}, %2;" : "=f"(lo), "=f"(hi) : "l"(v));
}
__device__ __forceinline__ void ffma2(ull &d, ull a, ull b) {
    asm("fma.rn.f32x2 %0, %1, %2, %0;" : "+l"(d) : "l"(a), "l"(b));
}
__device__ __forceinline__ void fadd2(ull &d, ull a) {
    asm("add.rn.f32x2 %0, %0, %1;" : "+l"(d) : "l"(a));
}
__device__ __forceinline__ void cp16(uint32_t dst, const void* src) {
    asm volatile("cp.async.cg.shared.global [%0], [%1], 16;\n" :: "r"(dst), "l"(src));
}

// Dynamic smem:
//   [0, 65536)       feat 128ch x 32 f4, XOR-swizzled (aliased by red buf)
//   [65536, 72192)   score 13 x 32 f4
#define SMEM_BYTES 72192
extern __shared__ unsigned char smem_raw[];

// ======================================================================
// CTA = (n, 128-channel tile). 8 warps = 2 channel-groups x 4 hw-slices.
// Thread (chg, sl, cp): channels {chg*64 + 2cp, +1}, hw [sl*32, sl*32+32),
// ALL 13 keypoints (no k-split -> feat tile read once from SMEM).
// f32x2 lanes = adjacent hw pairs straight from LDS.128 register pairs.
// ======================================================================
__global__ __launch_bounds__(NTHR, 3) void horeid_feat_kernel(
    const float* __restrict__ feat,
    const float* __restrict__ sco,
    float* __restrict__ out)
{
    float4* sfeat = reinterpret_cast<float4*>(smem_raw);
    float4* ssco  = reinterpret_cast<float4*>(smem_raw + 65536);
    float2* red2  = reinterpret_cast<float2*>(smem_raw);   // alias after sync
    float*  red   = reinterpret_cast<float*>(smem_raw);

    const int t   = threadIdx.x;
    const int n   = blockIdx.x >> 4;          // 16 tiles per batch row
    const int c0  = (blockIdx.x & 15) * TC;
    const int w   = t >> 5;
    const int chg = w >> 2;                   // channel group (warp-uniform)
    const int sl  = w & 3;                    // hw slice (warp-uniform)
    const int cp  = t & 31;                   // channel pair within group

    const uint32_t fbase = (uint32_t)__cvta_generic_to_shared(smem_raw);

    // ---- async load scoremap (416 f4) ----
    const float4* g_sco = reinterpret_cast<const float4*>(sco + (size_t)n * (KPT * HW_));
    for (int g = t; g < KPT * 32; g += NTHR)
        cp16(fbase + 65536u + (uint32_t)g * 16u, g_sco + g);

    // ---- async load feat tile (4096 f4), swizzle col ^ ((ch>>1)&7) ----
    const float4* g_feat = reinterpret_cast<const float4*>(
        feat + ((size_t)n * CCH + c0) * HW_);
#pragma unroll
    for (int i = 0; i < 16; ++i) {
        int g  = t + i * NTHR;
        int ch = g >> 5, cl = g & 31;
        cp16(fbase + (uint32_t)(ch * 32 + (cl ^ ((ch >> 1) & 7))) * 16u, g_feat + g);
    }
    asm volatile("cp.async.commit_group;\n");
    asm volatile("cp.async.wait_group 0;\n");
    __syncthreads();

    ull acc0[KPT], acc1[KPT];
#pragma unroll
    for (int k = 0; k < KPT; ++k) { acc0[k] = 0ull; acc1[k] = 0ull; }
    ull sum0 = 0ull, sum1 = 0ull;
    float mx0 = -3.402823466e38f, mx1 = mx0;

    const int chbase = chg * 64 + 2 * cp;     // even channel of this lane's pair
    const float4* fr0 = &sfeat[chbase * 32];
    const float4* fr1 = fr0 + 32;
    const int swz = cp & 7;                   // (chbase>>1)&7 == cp&7

#pragma unroll
    for (int jj = 0; jj < 8; ++jj) {
        const int j    = sl * 8 + jj;         // f4 column (warp-uniform)
        const int colx = j ^ swz;

        float4 f0 = fr0[colx];
        float4 f1 = fr1[colx];
        ull a0 = reinterpret_cast<ull*>(&f0)[0];
        ull a1 = reinterpret_cast<ull*>(&f0)[1];
        ull b0 = reinterpret_cast<ull*>(&f1)[0];
        ull b1 = reinterpret_cast<ull*>(&f1)[1];

        fadd2(sum0, a0); fadd2(sum0, a1);
        fadd2(sum1, b0); fadd2(sum1, b1);
        mx0 = fmaxf(mx0, fmaxf(fmaxf(f0.x, f0.y), fmaxf(f0.z, f0.w)));
        mx1 = fmaxf(mx1, fmaxf(fmaxf(f1.x, f1.y), fmaxf(f1.z, f1.w)));

#pragma unroll
        for (int k = 0; k < KPT; ++k) {
            float4 sv = ssco[k * 32 + j];     // uniform broadcast
            ull s01 = reinterpret_cast<ull*>(&sv)[0];
            ull s23 = reinterpret_cast<ull*>(&sv)[1];
            ffma2(acc0[k], s01, a0); ffma2(acc0[k], s23, a1);
            ffma2(acc1[k], s01, b0); ffma2(acc1[k], s23, b1);
        }
    }
    __syncthreads();   // done reading sfeat; alias as reduction buffer

    // ---- stage partials: red[slot*512 + sl*128 + ch], slot 0..12 = k,
    //      13 = spatial sum, 14 = spatial max.  (15*512*4B = 30.7 KB) ----
#pragma unroll
    for (int k = 0; k < KPT; ++k) {
        float l0, h0, l1, h1;
        upk2(acc0[k], l0, h0);
        upk2(acc1[k], l1, h1);
        red2[(k * 512 + sl * 128 + chbase) >> 1] = make_float2(l0 + h0, l1 + h1);
    }
    {
        float l0, h0, l1, h1;
        upk2(sum0, l0, h0);
        upk2(sum1, l1, h1);
        red2[(13 * 512 + sl * 128 + chbase) >> 1] = make_float2(l0 + h0, l1 + h1);
        red2[(14 * 512 + sl * 128 + chbase) >> 1] = make_float2(mx0, mx1);
    }
    __syncthreads();

    // ---- fold 4 slices, write coalesced (14*128 = 1792 = 7*256 outputs) ----
    float* ob = out + (size_t)n * (14 * CCH) + c0;
#pragma unroll
    for (int it = 0; it < 7; ++it) {
        const int idx  = t + it * NTHR;
        const int slot = idx >> 7, ch = idx & 127;
        if (slot < 13) {
            float v = red[slot * 512 + ch]       + red[slot * 512 + 128 + ch]
                    + red[slot * 512 + 256 + ch] + red[slot * 512 + 384 + ch];
            ob[slot * CCH + ch] = v;
        } else {
            float v = red[13 * 512 + ch]       + red[13 * 512 + 128 + ch]
                    + red[13 * 512 + 256 + ch] + red[13 * 512 + 384 + ch];
            float m = fmaxf(fmaxf(red[14 * 512 + ch],       red[14 * 512 + 128 + ch]),
                            fmaxf(red[14 * 512 + 256 + ch], red[14 * 512 + 384 + ch]));
            ob[13 * CCH + ch] = v * (1.0f / 128.0f) + m;
        }
    }
}

// ======================================================================
// Confidence kernel: L1-normalize 13 confidences per n, append 1.0.
// ======================================================================
__global__ __launch_bounds__(NBAT) void horeid_conf_kernel(
    const float* __restrict__ kc,
    float* __restrict__ out2)
{
    const int n = threadIdx.x;
    const float* r = kc + n * KPT;
    float v[KPT];
    float sm = 0.0f;
#pragma unroll
    for (int i = 0; i < KPT; ++i) { v[i] = r[i]; sm += fabsf(v[i]); }
    sm = fmaxf(sm, 1e-12f);
    const float inv = 1.0f / sm;
    float* o = out2 + n * 14;
#pragma unroll
    for (int i = 0; i < KPT; ++i) o[i] = v[i] * inv;
    o[KPT] = 1.0f;
}

// ======================================================================
extern "C" void kernel_launch(void* const* d_in, const int* in_sizes, int n_in,
                              void* d_out, int out_size)
{
    const float* feat = nullptr;
    const float* sco  = nullptr;
    const float* kc   = nullptr;
    for (int i = 0; i < n_in; ++i) {
        if (in_sizes[i] == NBAT * CCH * HW_)      feat = (const float*)d_in[i];
        else if (in_sizes[i] == NBAT * KPT * HW_) sco  = (const float*)d_in[i];
        else if (in_sizes[i] == NBAT * KPT)       kc   = (const float*)d_in[i];
    }
    float* out = (float*)d_out;

    cudaFuncSetAttribute(horeid_feat_kernel,
                         cudaFuncAttributeMaxDynamicSharedMemorySize, SMEM_BYTES);

    // conf first so ncu (-s 5 -c 1) lands on the main kernel
    horeid_conf_kernel<<<1, NBAT>>>(kc, out + (size_t)NBAT * 14 * CCH);
    horeid_feat_kernel<<<NBAT * 16, NTHR, SMEM_BYTES>>>(feat, sco, out);
    (void)out_size;
}

// round 14
// speedup vs baseline: 1.0240x; 1.0240x over previous
#include <cuda_runtime.h>
#include <cstdint>
#include <cstddef>

// Problem constants (fixed by reference: N=256, C=2048, H=16, W=8, K=13)
#define KPT   13
#define HW_   128
#define CCH   2048
#define NBAT  256
#define TC    64      // channels per tile
#define NTHR  256
#define TILES 8       // tiles per CTA (64ch each; 4 CTA-groups cover 2048 ch)

typedef unsigned long long ull;

__device__ __forceinline__ void upk2(ull v, float &lo, float &hi) {
    asm("mov.b64 {%0, %1}, %2;" : "=f"(lo), "=f"(hi) : "l"(v));
}
__device__ __forceinline__ void ffma2(ull &d, ull a, ull b) {
    asm("fma.rn.f32x2 %0, %1, %2, %0;" : "+l"(d) : "l"(a), "l"(b));
}
__device__ __forceinline__ void fadd2(ull &d, ull a) {
    asm("add.rn.f32x2 %0, %0, %1;" : "+l"(d) : "l"(a));
}
__device__ __forceinline__ void cp16(uint32_t dst, const void* src) {
    asm volatile("cp.async.cg.shared.global [%0], [%1], 16;\n" :: "r"(dst), "l"(src));
}

// Dynamic smem:
//   [0, 32768)       feat buffer A (64ch x 32 f4, swizzled; aliased by red buf)
//   [32768, 65536)   feat buffer B
//   [65536, 72192)   score 13 x 32 f4 (loaded once per CTA)
#define SMEM_BYTES 72192
extern __shared__ unsigned char smem_raw[];

// ======================================================================
// CTA = (n, channel-group of 8 tiles x 64ch). Double-buffered inter-tile
// pipeline: compute tile i from buf(i&1) while tile i+1 loads; prefetch
// tile i+2 right after tile i's reduction. Score loaded once (fixed n).
// Within a tile: R9 split-K structure — warps 0-3 k in [0,7), warps 4-7
// k in [7,13); thread (kg, sl, cp) owns channels {2cp,2cp+1}, hw slice
// [sl*32, sl*32+32). f32x2 lanes = adjacent hw pairs from LDS.128 pairs.
// ======================================================================
__global__ __launch_bounds__(NTHR, 3) void horeid_feat_kernel(
    const float* __restrict__ feat,
    const float* __restrict__ sco,
    float* __restrict__ out)
{
    const int t   = threadIdx.x;
    const int n   = blockIdx.x >> 2;         // 4 groups per batch row
    const int grp = blockIdx.x & 3;
    const int kg  = t >> 7;                  // k-group (warp-uniform)
    const int sl  = (t >> 5) & 3;            // hw slice (warp-uniform)
    const int cp  = t & 31;                  // channel pair (lane)
    const int kbase = kg * 7;
    const int kn    = kg ? 6 : 7;

    const uint32_t fb = (uint32_t)__cvta_generic_to_shared(smem_raw);
    const float4* ssco = reinterpret_cast<const float4*>(smem_raw + 65536);

    // ---- prologue: score (once) + tile0 as group0; tile1 as group1 ----
    const float4* g_sco = reinterpret_cast<const float4*>(sco + (size_t)n * (KPT * HW_));
    for (int g = t; g < KPT * 32; g += NTHR)
        cp16(fb + 65536u + (uint32_t)g * 16u, g_sco + g);

    const float* featn = feat + (size_t)n * CCH * HW_;

    // tile loader: 2048 f4 coalesced, swizzle col ^ ((ch>>1)&7)
    auto load_tile = [&](int i, uint32_t bufoff) {
        const float4* g_feat = reinterpret_cast<const float4*>(
            featn + (size_t)(grp * TILES + i) * TC * HW_);
#pragma unroll
        for (int r = 0; r < 8; ++r) {
            int g  = t + r * NTHR;
            int ch = g >> 5, cl = g & 31;
            cp16(fb + bufoff + (uint32_t)(ch * 32 + (cl ^ ((ch >> 1) & 7))) * 16u,
                 g_feat + g);
        }
    };

    load_tile(0, 0u);
    asm volatile("cp.async.commit_group;\n");      // g0: score + tile0
    load_tile(1, 32768u);
    asm volatile("cp.async.commit_group;\n");      // g1: tile1

    for (int i = 0; i < TILES; ++i) {
        const uint32_t bufoff = (uint32_t)(i & 1) * 32768u;
        float4* sfeat = reinterpret_cast<float4*>(smem_raw + bufoff);
        float2* red2  = reinterpret_cast<float2*>(smem_raw + bufoff);
        float*  red   = reinterpret_cast<float*>(smem_raw + bufoff);

        // tile i's group done; tile i+1 may stay in flight
        asm volatile("cp.async.wait_group 1;\n");
        __syncthreads();

        // ---- compute ----
        ull acc0[7], acc1[7];
#pragma unroll
        for (int kk = 0; kk < 7; ++kk) { acc0[kk] = 0ull; acc1[kk] = 0ull; }
        ull sum0 = 0ull, sum1 = 0ull;
        float mx0 = -3.402823466e38f, mx1 = mx0;

        const float4* fr0 = &sfeat[(2 * cp) * 32];
        const float4* fr1 = fr0 + 32;
        const int swz = cp & 7;

#pragma unroll
        for (int jj = 0; jj < 8; ++jj) {
            const int j    = sl * 8 + jj;        // f4 column (warp-uniform)
            const int colx = j ^ swz;

            float4 f0 = fr0[colx];
            float4 f1 = fr1[colx];
            ull a0 = reinterpret_cast<ull*>(&f0)[0];
            ull a1 = reinterpret_cast<ull*>(&f0)[1];
            ull b0 = reinterpret_cast<ull*>(&f1)[0];
            ull b1 = reinterpret_cast<ull*>(&f1)[1];

            if (kg == 0) {                        // warp-uniform branch
                fadd2(sum0, a0); fadd2(sum0, a1);
                fadd2(sum1, b0); fadd2(sum1, b1);
                mx0 = fmaxf(mx0, fmaxf(fmaxf(f0.x, f0.y), fmaxf(f0.z, f0.w)));
                mx1 = fmaxf(mx1, fmaxf(fmaxf(f1.x, f1.y), fmaxf(f1.z, f1.w)));
            }

#pragma unroll
            for (int kk = 0; kk < 7; ++kk) {
                if (kk < kn) {                    // warp-uniform predicate
                    float4 sv = ssco[(kbase + kk) * 32 + j];   // uniform bcast
                    ull s01 = reinterpret_cast<const ull*>(&sv)[0];
                    ull s23 = reinterpret_cast<const ull*>(&sv)[1];
                    ffma2(acc0[kk], s01, a0); ffma2(acc0[kk], s23, a1);
                    ffma2(acc1[kk], s01, b0); ffma2(acc1[kk], s23, b1);
                }
            }
        }
        __syncthreads();   // all reads of this feat buffer done -> alias as red

        // ---- stage partials: red2[slot*128 + sl*32 + cp] = (ch0, ch1) ----
#pragma unroll
        for (int kk = 0; kk < 7; ++kk) {
            if (kk < kn) {
                float l0, h0, l1, h1;
                upk2(acc0[kk], l0, h0);
                upk2(acc1[kk], l1, h1);
                red2[(kbase + kk) * 128 + sl * 32 + cp] = make_float2(l0 + h0, l1 + h1);
            }
        }
        if (kg == 0) {
            float l0, h0, l1, h1;
            upk2(sum0, l0, h0);
            upk2(sum1, l1, h1);
            red2[13 * 128 + sl * 32 + cp] = make_float2(l0 + h0, l1 + h1);
            red2[14 * 128 + sl * 32 + cp] = make_float2(mx0, mx1);
        }
        __syncthreads();

        // ---- fold 4 slices, write coalesced (14*64 = 896 outputs) ----
        const int c0 = (grp * TILES + i) * TC;
        float* ob = out + (size_t)n * (14 * CCH) + c0;
#pragma unroll
        for (int it = 0; it < 4; ++it) {
            const int idx = t + it * NTHR;
            if (idx < 14 * TC) {
                const int slot = idx >> 6, ch = idx & 63;
                if (slot < 13) {
                    float v = red[slot * 256 + ch]       + red[slot * 256 + 64 + ch]
                            + red[slot * 256 + 128 + ch] + red[slot * 256 + 192 + ch];
                    ob[slot * CCH + ch] = v;
                } else {
                    float v = red[13 * 256 + ch]       + red[13 * 256 + 64 + ch]
                            + red[13 * 256 + 128 + ch] + red[13 * 256 + 192 + ch];
                    float m = fmaxf(fmaxf(red[14 * 256 + ch],       red[14 * 256 + 64 + ch]),
                                    fmaxf(red[14 * 256 + 128 + ch], red[14 * 256 + 192 + ch]));
                    ob[13 * CCH + ch] = v * (1.0f / 128.0f) + m;
                }
            }
        }
        __syncthreads();   // red reads done before refilling this buffer

        // ---- prefetch tile i+2 into this buffer; always commit a group ----
        if (i + 2 < TILES) load_tile(i + 2, bufoff);
        asm volatile("cp.async.commit_group;\n");
    }
}

// ======================================================================
// Confidence kernel: L1-normalize 13 confidences per n, append 1.0.
// ======================================================================
__global__ __launch_bounds__(NBAT) void horeid_conf_kernel(
    const float* __restrict__ kc,
    float* __restrict__ out2)
{
    const int n = threadIdx.x;
    const float* r = kc + n * KPT;
    float v[KPT];
    float sm = 0.0f;
#pragma unroll
    for (int i = 0; i < KPT; ++i) { v[i] = r[i]; sm += fabsf(v[i]); }
    sm = fmaxf(sm, 1e-12f);
    const float inv = 1.0f / sm;
    float* o = out2 + n * 14;
#pragma unroll
    for (int i = 0; i < KPT; ++i) o[i] = v[i] * inv;
    o[KPT] = 1.0f;
}

// ======================================================================
extern "C" void kernel_launch(void* const* d_in, const int* in_sizes, int n_in,
                              void* d_out, int out_size)
{
    const float* feat = nullptr;
    const float* sco  = nullptr;
    const float* kc   = nullptr;
    for (int i = 0; i < n_in; ++i) {
        if (in_sizes[i] == NBAT * CCH * HW_)      feat = (const float*)d_in[i];
        else if (in_sizes[i] == NBAT * KPT * HW_) sco  = (const float*)d_in[i];
        else if (in_sizes[i] == NBAT * KPT)       kc   = (const float*)d_in[i];
    }
    float* out = (float*)d_out;

    cudaFuncSetAttribute(horeid_feat_kernel,
                         cudaFuncAttributeMaxDynamicSharedMemorySize, SMEM_BYTES);

    // conf first so ncu (-s 5 -c 1) lands on the main kernel
    horeid_conf_kernel<<<1, NBAT>>>(kc, out + (size_t)NBAT * 14 * CCH);
    horeid_feat_kernel<<<NBAT * 4, NTHR, SMEM_BYTES>>>(feat, sco, out);
    (void)out_size;
}